// round 1
// baseline (speedup 1.0000x reference)
#include <cuda_runtime.h>

#define N_NODES 50000
#define N_EDGES 200000
#define OUTD 32
#define IN_SELF 128
#define EDGE_DIM 16

// Scratch (allocation-free rule: __device__ globals)
__device__ float g_agg[N_NODES * OUTD];   // 6.4 MB, L2-resident
__device__ float g_deg[N_NODES];
__device__ float g_Wsum[EDGE_DIM * OUTD]; // transposed [k][j]
__device__ float g_bsum[OUTD];

// ---------------------------------------------------------------------------
// Kernel A: zero agg/deg; block 0 additionally reduces W_edge -> Wsum, bsum.
// Wsum[j,k] = sum_i W_edge[(i*32+j)*16 + k]   (stored transposed [k][j])
// bsum[j]   = sum_i b_edge[i*32+j]
// ---------------------------------------------------------------------------
__global__ void prep_kernel(const float* __restrict__ W_edge,
                            const float* __restrict__ b_edge) {
    int tid = blockIdx.x * blockDim.x + threadIdx.x;
    int stride = gridDim.x * blockDim.x;
    for (int i = tid; i < N_NODES * OUTD; i += stride) g_agg[i] = 0.f;
    for (int i = tid; i < N_NODES; i += stride) g_deg[i] = 0.f;

    if (blockIdx.x == 0) {
        int t = threadIdx.x;
        if (t < OUTD * EDGE_DIM) {
            int j = t / EDGE_DIM, k = t % EDGE_DIM;
            float s = 0.f;
            #pragma unroll
            for (int i = 0; i < OUTD; i++)
                s += W_edge[(i * OUTD + j) * EDGE_DIM + k];
            g_Wsum[k * OUTD + j] = s;
        }
        if (t < OUTD) {
            float s = 0.f;
            #pragma unroll
            for (int i = 0; i < OUTD; i++)
                s += b_edge[i * OUTD + t];
            g_bsum[t] = s;
        }
    }
}

// ---------------------------------------------------------------------------
// Kernel B: one warp per edge (grid-stride).
//   colsum[j] = ef[e] . Wsum[:,j] + bsum[j]   (ef broadcast via shfl)
//   s[j]      = h_neigh[src[e], j] * colsum[j]
//   atomicAdd(agg[dst[e], j], s[j]);  lane0: atomicAdd(deg[dst], 1)
// ---------------------------------------------------------------------------
__global__ void edge_kernel(const float* __restrict__ h_neigh,
                            const float* __restrict__ edge_features,
                            const int* __restrict__ src,
                            const int* __restrict__ dst) {
    __shared__ float sW[EDGE_DIM * OUTD];
    __shared__ float sb[OUTD];
    for (int i = threadIdx.x; i < EDGE_DIM * OUTD; i += blockDim.x)
        sW[i] = g_Wsum[i];
    if (threadIdx.x < OUTD) sb[threadIdx.x] = g_bsum[threadIdx.x];
    __syncthreads();

    const int lane = threadIdx.x & 31;
    const int warp = threadIdx.x >> 5;
    const int wpb = blockDim.x >> 5;
    const int nwarps = gridDim.x * wpb;

    for (int e = blockIdx.x * wpb + warp; e < N_EDGES; e += nwarps) {
        int s = src[e];
        int d = dst[e];
        // coalesced 64B load of the 16 edge features, broadcast via shfl
        float efv = (lane < EDGE_DIM) ? edge_features[e * EDGE_DIM + lane] : 0.f;
        float acc = sb[lane];
        #pragma unroll
        for (int k = 0; k < EDGE_DIM; k++) {
            float ek = __shfl_sync(0xffffffffu, efv, k);
            acc = fmaf(ek, sW[k * OUTD + lane], acc);
        }
        float hv = h_neigh[s * OUTD + lane];  // coalesced 128B row, L2-resident
        atomicAdd(&g_agg[d * OUTD + lane], hv * acc);
        if (lane == 0) atomicAdd(&g_deg[d], 1.0f);
    }
}

// ---------------------------------------------------------------------------
// Kernel C: one warp per node (grid-stride). Lane i owns output channel i.
//   z[n,i] = relu( h_self[n] . W_self[i]  +  (agg[n]/max(deg,1)) . W_neigh[i] )
// Weights staged in shared, TRANSPOSED so lane-indexed reads are conflict-free.
// h_self row held in registers (float4/lane), broadcast via shfl.
// ---------------------------------------------------------------------------
__global__ void node_kernel(const float* __restrict__ h_self,
                            const float* __restrict__ W_self,
                            const float* __restrict__ W_neigh,
                            float* __restrict__ out) {
    __shared__ float sWs[IN_SELF * OUTD]; // [m][i]
    __shared__ float sWn[OUTD * OUTD];    // [m][i]
    for (int t = threadIdx.x; t < OUTD * IN_SELF; t += blockDim.x) {
        int i = t / IN_SELF, m = t % IN_SELF;
        sWs[m * OUTD + i] = W_self[t];
    }
    for (int t = threadIdx.x; t < OUTD * OUTD; t += blockDim.x) {
        int i = t / OUTD, m = t % OUTD;
        sWn[m * OUTD + i] = W_neigh[t];
    }
    __syncthreads();

    const int lane = threadIdx.x & 31;
    const int warp = threadIdx.x >> 5;
    const int wpb = blockDim.x >> 5;
    const int nwarps = gridDim.x * wpb;

    for (int n = blockIdx.x * wpb + warp; n < N_NODES; n += nwarps) {
        float4 hs = *reinterpret_cast<const float4*>(
            &h_self[n * IN_SELF + lane * 4]);
        float inv = 1.0f / fmaxf(g_deg[n], 1.0f);
        float aggv = g_agg[n * OUTD + lane] * inv;

        float acc = 0.f;
        #pragma unroll
        for (int g = 0; g < 32; g++) {
            float a = __shfl_sync(0xffffffffu, hs.x, g);
            float b = __shfl_sync(0xffffffffu, hs.y, g);
            float c = __shfl_sync(0xffffffffu, hs.z, g);
            float d = __shfl_sync(0xffffffffu, hs.w, g);
            acc = fmaf(a, sWs[(g * 4 + 0) * OUTD + lane], acc);
            acc = fmaf(b, sWs[(g * 4 + 1) * OUTD + lane], acc);
            acc = fmaf(c, sWs[(g * 4 + 2) * OUTD + lane], acc);
            acc = fmaf(d, sWs[(g * 4 + 3) * OUTD + lane], acc);
        }
        #pragma unroll
        for (int m = 0; m < OUTD; m++) {
            float av = __shfl_sync(0xffffffffu, aggv, m);
            acc = fmaf(av, sWn[m * OUTD + lane], acc);
        }
        out[n * OUTD + lane] = fmaxf(acc, 0.f);
    }
}

extern "C" void kernel_launch(void* const* d_in, const int* in_sizes, int n_in,
                              void* d_out, int out_size) {
    const float* h_neigh       = (const float*)d_in[0];
    const float* h_self        = (const float*)d_in[1];
    const float* edge_features = (const float*)d_in[2];
    const float* W_edge        = (const float*)d_in[3];
    const float* b_edge        = (const float*)d_in[4];
    const float* W_self        = (const float*)d_in[5];
    const float* W_neigh       = (const float*)d_in[6];
    const int*   src           = (const int*)d_in[7];
    const int*   dst           = (const int*)d_in[8];
    float* out = (float*)d_out;

    prep_kernel<<<512, 512>>>(W_edge, b_edge);
    edge_kernel<<<1184, 256>>>(h_neigh, edge_features, src, dst);
    node_kernel<<<1184, 256>>>(h_self, W_self, W_neigh, out);
}

// round 2
// speedup vs baseline: 1.5753x; 1.5753x over previous
#include <cuda_runtime.h>

#define N_NODES 50000
#define N_EDGES 200000
#define OUTD 32
#define IN_SELF 128
#define EDGE_DIM 16

#define EDGE_BLOCKS 296
#define EDGE_THREADS 512
#define NODE_BLOCKS 592
#define NODE_THREADS 256

// Scratch: agg [N_NODES*32] followed by deg [N_NODES] in one symbol (one memset)
__device__ float g_scratch[N_NODES * OUTD + N_NODES];

__device__ __forceinline__ void red_add_v4(float* ptr, float4 v) {
    asm volatile("red.global.add.v4.f32 [%0], {%1, %2, %3, %4};"
                 :: "l"(ptr), "f"(v.x), "f"(v.y), "f"(v.z), "f"(v.w)
                 : "memory");
}

// ---------------------------------------------------------------------------
// Edge kernel: each block first reduces W_edge -> colsum weights in shared
// (Wsum[k][j] = sum_i W_edge[(i*32+j)*16+k], bsum[j] = sum_i b_edge[i*32+j]).
// Then 4 edges per warp: 8 lanes/edge, 4 channels/lane.
//   colsum[e, 4p..4p+3] = ef[e] . Wsum[:, 4p..4p+3] + bsum
//   msg = h_neigh[src[e], 4p..4p+3] * colsum
//   red.global.add.v4(agg[dst[e], 4p..4p+3], msg); p==0: red(deg[dst], 1)
// ---------------------------------------------------------------------------
__global__ void __launch_bounds__(EDGE_THREADS)
edge_kernel(const float* __restrict__ h_neigh,
            const float* __restrict__ edge_features,
            const float* __restrict__ W_edge,
            const float* __restrict__ b_edge,
            const int* __restrict__ src,
            const int* __restrict__ dst) {
    __shared__ __align__(16) float sW[EDGE_DIM * OUTD]; // [k][j]
    __shared__ __align__(16) float sb[OUTD];

    // Per-block Wsum reduction (512 threads == 512 outputs)
    {
        int t = threadIdx.x;
        int j = t >> 4, k = t & 15;
        float s = 0.f;
        #pragma unroll
        for (int i = 0; i < OUTD; i++)
            s += W_edge[(i * OUTD + j) * EDGE_DIM + k];
        sW[k * OUTD + j] = s;
        if (t < OUTD) {
            float s2 = 0.f;
            #pragma unroll
            for (int i = 0; i < OUTD; i++)
                s2 += b_edge[i * OUTD + t];
            sb[t] = s2;
        }
    }
    __syncthreads();

    float* g_agg = g_scratch;
    float* g_deg = g_scratch + N_NODES * OUTD;

    const int lane = threadIdx.x & 31;
    const int warp = threadIdx.x >> 5;
    const int g = lane >> 3;   // edge group within warp (0..3)
    const int p = lane & 7;    // channel quad within edge (0..7)
    const int wpb = EDGE_THREADS >> 5;
    const int nwarps = EDGE_BLOCKS * wpb;
    const int NGROUPS = N_EDGES / 4; // 50000

    for (int grp = blockIdx.x * wpb + warp; grp < NGROUPS; grp += nwarps) {
        int e0 = grp * 4;
        int e = e0 + g;
        int s = src[e];
        int d = dst[e];

        // lane holds ef[e0+g][2p], ef[e0+g][2p+1] (coalesced 256B/warp)
        float2 ef = *reinterpret_cast<const float2*>(
            &edge_features[e0 * EDGE_DIM + lane * 2]);

        float4 acc = *reinterpret_cast<const float4*>(&sb[4 * p]);
        #pragma unroll
        for (int k = 0; k < EDGE_DIM; k++) {
            float ek = __shfl_sync(0xffffffffu, (k & 1) ? ef.y : ef.x, k >> 1, 8);
            float4 w = *reinterpret_cast<const float4*>(&sW[k * OUTD + 4 * p]);
            acc.x = fmaf(ek, w.x, acc.x);
            acc.y = fmaf(ek, w.y, acc.y);
            acc.z = fmaf(ek, w.z, acc.z);
            acc.w = fmaf(ek, w.w, acc.w);
        }

        float4 hv = *reinterpret_cast<const float4*>(&h_neigh[s * OUTD + 4 * p]);
        float4 msg = make_float4(hv.x * acc.x, hv.y * acc.y,
                                 hv.z * acc.z, hv.w * acc.w);
        red_add_v4(&g_agg[d * OUTD + 4 * p], msg);
        if (p == 0) atomicAdd(&g_deg[d], 1.0f);
    }
}

// ---------------------------------------------------------------------------
// Node kernel: one warp per node (grid-stride), lane i = output channel i.
// Weights staged in shared, row-per-output with padded stride (conflict-free
// LDS.128). h_self row + normalized agg staged per warp in shared; broadcast
// reads via uniform-address LDS.128.
// ---------------------------------------------------------------------------
#define WS_PAD 132   // 128 + 4 floats
#define WN_PAD 36    // 32 + 4 floats

__global__ void __launch_bounds__(NODE_THREADS)
node_kernel(const float* __restrict__ h_self,
            const float* __restrict__ W_self,
            const float* __restrict__ W_neigh,
            float* __restrict__ out) {
    __shared__ __align__(16) float sWs[OUTD * WS_PAD];
    __shared__ __align__(16) float sWn[OUTD * WN_PAD];
    __shared__ __align__(16) float sh[NODE_THREADS / 32][IN_SELF + OUTD];

    for (int t = threadIdx.x; t < OUTD * IN_SELF; t += NODE_THREADS) {
        int i = t >> 7, m = t & 127;
        sWs[i * WS_PAD + m] = W_self[t];
    }
    for (int t = threadIdx.x; t < OUTD * OUTD; t += NODE_THREADS) {
        int i = t >> 5, m = t & 31;
        sWn[i * WN_PAD + m] = W_neigh[t];
    }
    __syncthreads();

    const float* g_agg = g_scratch;
    const float* g_deg = g_scratch + N_NODES * OUTD;

    const int lane = threadIdx.x & 31;
    const int warp = threadIdx.x >> 5;
    const int wpb = NODE_THREADS >> 5;
    float* myh = sh[warp];

    for (int n = blockIdx.x * wpb + warp; n < N_NODES; n += NODE_BLOCKS * wpb) {
        // Stage h_self row (128 floats, LDG.128/lane) + normalized agg (32)
        float4 hld = *reinterpret_cast<const float4*>(&h_self[n * IN_SELF + lane * 4]);
        float inv = 1.0f / fmaxf(g_deg[n], 1.0f);
        float av = g_agg[n * OUTD + lane] * inv;
        *reinterpret_cast<float4*>(&myh[lane * 4]) = hld;
        myh[IN_SELF + lane] = av;
        __syncwarp();

        float acc = 0.f;
        #pragma unroll
        for (int m = 0; m < IN_SELF / 4; m++) {
            float4 h4 = *reinterpret_cast<const float4*>(&myh[m * 4]);       // broadcast
            float4 w4 = *reinterpret_cast<const float4*>(&sWs[lane * WS_PAD + m * 4]);
            acc = fmaf(h4.x, w4.x, acc);
            acc = fmaf(h4.y, w4.y, acc);
            acc = fmaf(h4.z, w4.z, acc);
            acc = fmaf(h4.w, w4.w, acc);
        }
        #pragma unroll
        for (int m = 0; m < OUTD / 4; m++) {
            float4 a4 = *reinterpret_cast<const float4*>(&myh[IN_SELF + m * 4]); // broadcast
            float4 w4 = *reinterpret_cast<const float4*>(&sWn[lane * WN_PAD + m * 4]);
            acc = fmaf(a4.x, w4.x, acc);
            acc = fmaf(a4.y, w4.y, acc);
            acc = fmaf(a4.z, w4.z, acc);
            acc = fmaf(a4.w, w4.w, acc);
        }
        out[n * OUTD + lane] = fmaxf(acc, 0.f);
        __syncwarp();
    }
}

extern "C" void kernel_launch(void* const* d_in, const int* in_sizes, int n_in,
                              void* d_out, int out_size) {
    const float* h_neigh       = (const float*)d_in[0];
    const float* h_self        = (const float*)d_in[1];
    const float* edge_features = (const float*)d_in[2];
    const float* W_edge        = (const float*)d_in[3];
    const float* b_edge        = (const float*)d_in[4];
    const float* W_self        = (const float*)d_in[5];
    const float* W_neigh       = (const float*)d_in[6];
    const int*   src           = (const int*)d_in[7];
    const int*   dst           = (const int*)d_in[8];
    float* out = (float*)d_out;

    void* scratch_ptr = nullptr;
    cudaGetSymbolAddress(&scratch_ptr, g_scratch);
    cudaMemsetAsync(scratch_ptr, 0, sizeof(float) * (N_NODES * OUTD + N_NODES), 0);

    edge_kernel<<<EDGE_BLOCKS, EDGE_THREADS>>>(h_neigh, edge_features,
                                               W_edge, b_edge, src, dst);
    node_kernel<<<NODE_BLOCKS, NODE_THREADS>>>(h_self, W_self, W_neigh, out);
}

// round 3
// speedup vs baseline: 2.6313x; 1.6704x over previous
#include <cuda_runtime.h>

#define N_NODES 50000
#define N_EDGES 200000
#define OUTD 32
#define IN_SELF 128
#define EDGE_DIM 16

#define EDGE_BLOCKS 296
#define EDGE_THREADS 512

// Node GEMM tiling
#define BN 128          // nodes per block tile
#define KB 32           // k-chunk
#define BNP 132         // padded node stride in shared
#define NODE_GEMM_THREADS 128

// Scratch: agg [N_NODES*32] followed by deg [N_NODES] in one symbol (one memset)
__device__ float g_scratch[N_NODES * OUTD + N_NODES];

__device__ __forceinline__ void red_add_v4(float* ptr, float4 v) {
    asm volatile("red.global.add.v4.f32 [%0], {%1, %2, %3, %4};"
                 :: "l"(ptr), "f"(v.x), "f"(v.y), "f"(v.z), "f"(v.w)
                 : "memory");
}

// ---------------------------------------------------------------------------
// Edge kernel (unchanged from R2): per-block Wsum reduction, then 4 edges per
// warp, 8 lanes/edge, 4 channels/lane, vectorized atomics into agg.
// ---------------------------------------------------------------------------
__global__ void __launch_bounds__(EDGE_THREADS)
edge_kernel(const float* __restrict__ h_neigh,
            const float* __restrict__ edge_features,
            const float* __restrict__ W_edge,
            const float* __restrict__ b_edge,
            const int* __restrict__ src,
            const int* __restrict__ dst) {
    __shared__ __align__(16) float sW[EDGE_DIM * OUTD]; // [k][j]
    __shared__ __align__(16) float sb[OUTD];

    {
        int t = threadIdx.x;
        int j = t >> 4, k = t & 15;
        float s = 0.f;
        #pragma unroll
        for (int i = 0; i < OUTD; i++)
            s += W_edge[(i * OUTD + j) * EDGE_DIM + k];
        sW[k * OUTD + j] = s;
        if (t < OUTD) {
            float s2 = 0.f;
            #pragma unroll
            for (int i = 0; i < OUTD; i++)
                s2 += b_edge[i * OUTD + t];
            sb[t] = s2;
        }
    }
    __syncthreads();

    float* g_agg = g_scratch;
    float* g_deg = g_scratch + N_NODES * OUTD;

    const int lane = threadIdx.x & 31;
    const int warp = threadIdx.x >> 5;
    const int g = lane >> 3;
    const int p = lane & 7;
    const int wpb = EDGE_THREADS >> 5;
    const int nwarps = EDGE_BLOCKS * wpb;
    const int NGROUPS = N_EDGES / 4;

    for (int grp = blockIdx.x * wpb + warp; grp < NGROUPS; grp += nwarps) {
        int e0 = grp * 4;
        int e = e0 + g;
        int s = src[e];
        int d = dst[e];

        float2 ef = *reinterpret_cast<const float2*>(
            &edge_features[e0 * EDGE_DIM + lane * 2]);

        float4 acc = *reinterpret_cast<const float4*>(&sb[4 * p]);
        #pragma unroll
        for (int k = 0; k < EDGE_DIM; k++) {
            float ek = __shfl_sync(0xffffffffu, (k & 1) ? ef.y : ef.x, k >> 1, 8);
            float4 w = *reinterpret_cast<const float4*>(&sW[k * OUTD + 4 * p]);
            acc.x = fmaf(ek, w.x, acc.x);
            acc.y = fmaf(ek, w.y, acc.y);
            acc.z = fmaf(ek, w.z, acc.z);
            acc.w = fmaf(ek, w.w, acc.w);
        }

        float4 hv = *reinterpret_cast<const float4*>(&h_neigh[s * OUTD + 4 * p]);
        float4 msg = make_float4(hv.x * acc.x, hv.y * acc.y,
                                 hv.z * acc.z, hv.w * acc.w);
        red_add_v4(&g_agg[d * OUTD + 4 * p], msg);
        if (p == 0) atomicAdd(&g_deg[d], 1.0f);
    }
}

// ---------------------------------------------------------------------------
// Node kernel: register-blocked GEMM.
//   out[n, c] = relu( sum_k X[n,k] * Wc[c,k] ),
//   X = [h_self | agg/deg] (K=160), Wc = [W_self | W_neigh].
// Block tile 128 nodes x 32 chans. 128 threads, each owns 8 nodes x 4 chans.
// K processed in 5 chunks of 32, staged transposed in shared.
// ---------------------------------------------------------------------------
__global__ void __launch_bounds__(NODE_GEMM_THREADS)
node_kernel(const float* __restrict__ h_self,
            const float* __restrict__ W_self,
            const float* __restrict__ W_neigh,
            float* __restrict__ out) {
    __shared__ __align__(16) float h_s[KB][BNP];
    __shared__ __align__(16) float w_s[KB][OUTD];
    __shared__ float sinv[BN];

    const float* g_agg = g_scratch;
    const float* g_deg = g_scratch + N_NODES * OUTD;

    const int t = threadIdx.x;
    const int nbase = blockIdx.x * BN;
    const int tn = t >> 3;   // 0..15 -> node octet
    const int tc = t & 7;    // 0..7  -> channel quad

    // inverse degree for this block's nodes
    {
        int gn = nbase + t;
        sinv[t] = (gn < N_NODES) ? 1.0f / fmaxf(g_deg[gn], 1.0f) : 0.f;
    }

    float acc[8][4];
    #pragma unroll
    for (int r = 0; r < 8; r++)
        #pragma unroll
        for (int c = 0; c < 4; c++) acc[r][c] = 0.f;

    #pragma unroll
    for (int kc = 0; kc < 5; kc++) {
        __syncthreads();
        // --- stage h chunk (transposed): 128 nodes x 32 k ---
        #pragma unroll
        for (int i = 0; i < 8; i++) {
            int idx = t + i * NODE_GEMM_THREADS;  // 0..1023
            int node = idx >> 3;                  // 0..127
            int kvec = idx & 7;                   // 0..7
            int gn = nbase + node;
            float4 v = make_float4(0.f, 0.f, 0.f, 0.f);
            if (gn < N_NODES) {
                if (kc < 4) {
                    v = *reinterpret_cast<const float4*>(
                        &h_self[gn * IN_SELF + kc * KB + kvec * 4]);
                } else {
                    v = *reinterpret_cast<const float4*>(
                        &g_agg[gn * OUTD + kvec * 4]);
                    float iv = sinv[node];
                    v.x *= iv; v.y *= iv; v.z *= iv; v.w *= iv;
                }
            }
            h_s[kvec * 4 + 0][node] = v.x;
            h_s[kvec * 4 + 1][node] = v.y;
            h_s[kvec * 4 + 2][node] = v.z;
            h_s[kvec * 4 + 3][node] = v.w;
        }
        // --- stage weight chunk (transposed): 32 chans x 32 k ---
        #pragma unroll
        for (int i = 0; i < 2; i++) {
            int idx = t + i * NODE_GEMM_THREADS;  // 0..255
            int chan = idx >> 3;                  // 0..31
            int kvec = idx & 7;                   // 0..7
            float4 w;
            if (kc < 4) {
                w = *reinterpret_cast<const float4*>(
                    &W_self[chan * IN_SELF + kc * KB + kvec * 4]);
            } else {
                w = *reinterpret_cast<const float4*>(
                    &W_neigh[chan * OUTD + kvec * 4]);
            }
            w_s[kvec * 4 + 0][chan] = w.x;
            w_s[kvec * 4 + 1][chan] = w.y;
            w_s[kvec * 4 + 2][chan] = w.z;
            w_s[kvec * 4 + 3][chan] = w.w;
        }
        __syncthreads();
        // --- compute: 32 k-steps, 32 FMAs each ---
        #pragma unroll
        for (int kk = 0; kk < KB; kk++) {
            float4 w  = *reinterpret_cast<const float4*>(&w_s[kk][tc * 4]);
            float4 h0 = *reinterpret_cast<const float4*>(&h_s[kk][tn * 8]);
            float4 h1 = *reinterpret_cast<const float4*>(&h_s[kk][tn * 8 + 4]);
            float hr[8] = {h0.x, h0.y, h0.z, h0.w, h1.x, h1.y, h1.z, h1.w};
            float wc[4] = {w.x, w.y, w.z, w.w};
            #pragma unroll
            for (int r = 0; r < 8; r++)
                #pragma unroll
                for (int c = 0; c < 4; c++)
                    acc[r][c] = fmaf(hr[r], wc[c], acc[r][c]);
        }
    }

    // --- epilogue: relu + store ---
    #pragma unroll
    for (int r = 0; r < 8; r++) {
        int gn = nbase + tn * 8 + r;
        if (gn < N_NODES) {
            float4 o = make_float4(fmaxf(acc[r][0], 0.f), fmaxf(acc[r][1], 0.f),
                                   fmaxf(acc[r][2], 0.f), fmaxf(acc[r][3], 0.f));
            *reinterpret_cast<float4*>(&out[gn * OUTD + tc * 4]) = o;
        }
    }
}

extern "C" void kernel_launch(void* const* d_in, const int* in_sizes, int n_in,
                              void* d_out, int out_size) {
    const float* h_neigh       = (const float*)d_in[0];
    const float* h_self        = (const float*)d_in[1];
    const float* edge_features = (const float*)d_in[2];
    const float* W_edge        = (const float*)d_in[3];
    const float* b_edge        = (const float*)d_in[4];
    const float* W_self        = (const float*)d_in[5];
    const float* W_neigh       = (const float*)d_in[6];
    const int*   src           = (const int*)d_in[7];
    const int*   dst           = (const int*)d_in[8];
    float* out = (float*)d_out;

    void* scratch_ptr = nullptr;
    cudaGetSymbolAddress(&scratch_ptr, g_scratch);
    cudaMemsetAsync(scratch_ptr, 0, sizeof(float) * (N_NODES * OUTD + N_NODES), 0);

    edge_kernel<<<EDGE_BLOCKS, EDGE_THREADS>>>(h_neigh, edge_features,
                                               W_edge, b_edge, src, dst);

    int node_blocks = (N_NODES + BN - 1) / BN;  // 391
    node_kernel<<<node_blocks, NODE_GEMM_THREADS>>>(h_self, W_self, W_neigh, out);
}